// round 7
// baseline (speedup 1.0000x reference)
#include <cuda_runtime.h>
#include <math.h>

#define BB 4
#define NN 512
#define HD 64
#define IDM 128
#define PI_F 3.14159265358979323846f
#define INV_SQRT2 0.70710678118654752440f
#define RPB 8            // rows per prep block

// tanh-based erf approx: erf(d) ~= tanh(C0*d + C1*d^3)
#define ERF_C0 1.1283791671f
#define ERF_C1 0.1009052923f

// Scratch (device globals: no allocation allowed)
__device__ __align__(16) float g_U2[BB*NN*IDM];   // (A@We1 + be1) / sqrt2
__device__ __align__(16) float g_V2[BB*NN*IDM];   // (C@We1)       / sqrt2
__device__ float g_SU[BB*NN];                     // 0.5 * dot(U, w2)
__device__ float g_SV[BB*NN];

typedef unsigned long long u64;

__device__ __forceinline__ u64 pack2(float lo, float hi) {
    u64 r; asm("mov.b64 %0, {%1, %2};" : "=l"(r) : "f"(lo), "f"(hi)); return r;
}
__device__ __forceinline__ void unpack2(u64 v, float& lo, float& hi) {
    asm("mov.b64 {%0, %1}, %2;" : "=f"(lo), "=f"(hi) : "l"(v));
}
__device__ __forceinline__ u64 fma2(u64 a, u64 b, u64 c) {
    u64 r; asm("fma.rn.f32x2 %0, %1, %2, %3;" : "=l"(r) : "l"(a), "l"(b), "l"(c)); return r;
}
__device__ __forceinline__ u64 add2(u64 a, u64 b) {
    u64 r; asm("add.rn.f32x2 %0, %1, %2;" : "=l"(r) : "l"(a), "l"(b)); return r;
}
__device__ __forceinline__ u64 mul2(u64 a, u64 b) {
    u64 r; asm("mul.rn.f32x2 %0, %1, %2;" : "=l"(r) : "l"(a), "l"(b)); return r;
}
__device__ __forceinline__ float fast_tanh(float x) {
    float y; asm("tanh.approx.f32 %0, %1;" : "=f"(y) : "f"(x)); return y;
}

// ---------------------------------------------------------------------------
// Precompute. 256 threads: ti = I-index (0..127), half = row-group (4 rows each).
// Row-split halves the per-thread FMA chain in phases 2/3 with no combine step.
// ---------------------------------------------------------------------------
__global__ __launch_bounds__(256) void prep_kernel(
    const float* __restrict__ bf,   const float* __restrict__ emb,
    const float* __restrict__ Wcls, const float* __restrict__ bcls,
    const float* __restrict__ Wpos, const float* __restrict__ bpos,
    const float* __restrict__ Win,  const float* __restrict__ bin,
    const float* __restrict__ Wout, const float* __restrict__ bout,
    const float* __restrict__ We1,  const float* __restrict__ be1,
    const float* __restrict__ We2)
{
    int t = threadIdx.x, lane = t & 31, wid = t >> 5;   // wid 0..7
    int ti = t & 127, half = t >> 7;                    // rows 4*half..4*half+3
    int row0 = blockIdx.x * RPB;

    __shared__ __align__(16) float xs[RPB][HD];
    __shared__ __align__(16) float featsT[HD][RPB];   // k-major
    __shared__ __align__(16) float ApreT[IDM][RPB];   // k-major
    __shared__ __align__(16) float BpreT[IDM][RPB];
    __shared__ float p0s[RPB], p1s[RPB];
    __shared__ float partU[8][4], partV[8][4];

    for (int idx = t; idx < RPB*HD; idx += 256)
        ((float*)xs)[idx] = bf[row0*HD + idx];

    if (t < RPB) {
        int row = row0 + t;
        float ang = emb[row*2 + 0] * PI_F;
        float rho = emb[row*2 + 1] * 800.0f;
        float tn = tanf(ang);
        float ic = 1.0f / cosf(ang);
        float lin1 = (1.0f - 1e-5f) / 71.0f;
        float y0 = 160.0f;
        float y1 = 160.0f - lin1 * 320.0f;
        p0s[t] = (-tn * y0 + rho * ic) * (1.0f / 800.0f);
        p1s[t] = (-tn * y1 + rho * ic) * (1.0f / 800.0f);
    }
    __syncthreads();

    // phase 1: feats = relu(x @ Wcls + bcls), 4 rows per pass
    {
        int d = t & 63, rq = t >> 6;     // rq 0..3
        float bc = bcls[d];
        #pragma unroll
        for (int pass = 0; pass < 2; pass++) {
            int r = rq + 4*pass;
            float acc = bc;
            #pragma unroll 8
            for (int k = 0; k < HD; k++) acc = fmaf(xs[r][k], Wcls[k*HD + d], acc);
            featsT[d][r] = fmaxf(acc, 0.0f);
        }
    }
    __syncthreads();

    // phase 2: f_in / f_out for this half's 4 rows (f32x2 packed)
    {
        float bi = bin[ti], bo = bout[ti];
        u64 ai01 = pack2(bi,bi), ai23 = ai01;
        u64 ao01 = pack2(bo,bo), ao23 = ao01;
        #pragma unroll 4
        for (int k = 0; k < HD; k++) {
            float win  = Win [k*IDM + ti];
            float wout = Wout[k*IDM + ti];
            u64 wi = pack2(win, win), wo = pack2(wout, wout);
            ulonglong2 fa = *(const ulonglong2*)&featsT[k][4*half];
            ai01 = fma2(fa.x, wi, ai01);  ao01 = fma2(fa.x, wo, ao01);
            ai23 = fma2(fa.y, wi, ai23);  ao23 = fma2(fa.y, wo, ao23);
        }
        float wp0 = Wpos[ti], wp1 = Wpos[IDM + ti], bp = bpos[ti];
        float pe0 = fmaf(p0s[4*half+0], wp0, p1s[4*half+0] * wp1);
        float pe1 = fmaf(p0s[4*half+1], wp0, p1s[4*half+1] * wp1);
        float pe2 = fmaf(p0s[4*half+2], wp0, p1s[4*half+2] * wp1);
        float pe3 = fmaf(p0s[4*half+3], wp0, p1s[4*half+3] * wp1);
        u64 bp2  = pack2(bp, bp);
        u64 pe01 = pack2(pe0, pe1), pe23 = pack2(pe2, pe3);
        u64* arow = (u64*)&ApreT[ti][4*half];
        u64* brow = (u64*)&BpreT[ti][4*half];
        arow[0] = add2(ai01, add2(pe01, bp2));
        arow[1] = add2(ai23, add2(pe23, bp2));
        brow[0] = add2(ao01, pe01);
        brow[1] = add2(ao23, pe23);
    }
    __syncthreads();

    // phase 3: U = Apre @ We1 + be1, V = Bpre @ We1 for this half's 4 rows
    float uu[4], vv[4];
    {
        float b1 = be1[ti];
        u64 u01 = pack2(b1,b1), u23 = u01;
        u64 v01 = 0ULL, v23 = 0ULL;
        #pragma unroll 4
        for (int k = 0; k < IDM; k++) {
            float w = We1[k*IDM + ti];
            u64 w2 = pack2(w, w);
            ulonglong2 aA = *(const ulonglong2*)&ApreT[k][4*half];
            ulonglong2 cA = *(const ulonglong2*)&BpreT[k][4*half];
            u01 = fma2(aA.x, w2, u01);  v01 = fma2(cA.x, w2, v01);
            u23 = fma2(aA.y, w2, u23);  v23 = fma2(cA.y, w2, v23);
        }
        u64 is2 = pack2(INV_SQRT2, INV_SQRT2);
        u01 = mul2(u01, is2); u23 = mul2(u23, is2);
        v01 = mul2(v01, is2); v23 = mul2(v23, is2);
        unpack2(u01, uu[0], uu[1]); unpack2(u23, uu[2], uu[3]);
        unpack2(v01, vv[0], vv[1]); unpack2(v23, vv[2], vv[3]);
    }

    float w2s = We2[ti] * INV_SQRT2;
    #pragma unroll
    for (int r = 0; r < 4; r++) {
        int row = row0 + 4*half + r;
        g_U2[row*IDM + ti] = uu[r];
        g_V2[row*IDM + ti] = vv[r];
        float su = uu[r] * w2s, sv = vv[r] * w2s;
        #pragma unroll
        for (int o = 16; o; o >>= 1) {
            su += __shfl_xor_sync(0xffffffffu, su, o);
            sv += __shfl_xor_sync(0xffffffffu, sv, o);
        }
        if (lane == 0) { partU[wid][r] = su; partV[wid][r] = sv; }
    }
    __syncthreads();
    if (t < RPB) {
        int r = t, h = r >> 2, rr = r & 3;
        g_SU[row0 + r] = partU[4*h][rr] + partU[4*h+1][rr]
                       + partU[4*h+2][rr] + partU[4*h+3][rr];
    } else if (t < 2*RPB) {
        int r = t - RPB, h = r >> 2, rr = r & 3;
        g_SV[row0 + r] = partV[4*h][rr] + partV[4*h+1][rr]
                       + partV[4*h+2][rr] + partV[4*h+3][rr];
    }
}

// ---------------------------------------------------------------------------
// Main: ONE column per 128-thread block (2048 blocks). Dead columns retire
// immediately. Each warp builds + consumes its own quarter-range list.
// Inner loop in packed f32x2 (13 fma-insts/entry), batch-8 segmented reduce.
// ---------------------------------------------------------------------------
__global__ __launch_bounds__(128) void main_kernel(
    const float* __restrict__ cls, const int* __restrict__ aid,
    const float* __restrict__ emb,
    const float* __restrict__ We2, const float* __restrict__ be2,
    const float* __restrict__ Wn1, const float* __restrict__ bn1,
    const float* __restrict__ Wn2, const float* __restrict__ bn2,
    const float* __restrict__ Wh,  const float* __restrict__ bh,
    float* __restrict__ out)
{
    __shared__ unsigned short lst_s[4][128];
    __shared__ float pmax_s[4];
    __shared__ float n1_s[HD];

    int t = threadIdx.x, lane = t & 31, w = t >> 5;
    int g = blockIdx.x;
    int b = g >> 9;

    float cj = __ldg(&cls[g]);
    if (cj < 0.4f) {                   // sigmoid(-1e6) == 0 in f32
        if (t == 0) out[g] = 0.0f;
        return;
    }
    float aj  = __ldg(&emb[2*g]) * PI_F;
    int   idj = __ldg(&aid[g]);

    // per-warp compacted list over i in [128w, 128w+128)
    int cnt = 0;
    {
        unsigned short* lst = lst_s[w];
        int gbase = b*NN + 128*w;
        #pragma unroll
        for (int c = 0; c < 128; c += 32) {
            int gi = gbase + c + lane;
            float ci = __ldg(&cls[gi]);
            float ai = __ldg(&emb[2*gi]) * PI_F;
            int  idi = __ldg(&aid[gi]);
            bool p = (fabsf(ai - aj) < 0.5f) &&
                     ((ci > cj) || ((ci == cj) && (idi > idj)));
            unsigned m = __ballot_sync(0xffffffffu, p);
            if (p) lst[cnt + __popc(m & ((1u << lane) - 1u))]
                       = (unsigned short)(128*w + c + lane);
            cnt += __popc(m);
        }
    }

    // per-column constants
    const float* gSUb = g_SU + b*NN;
    ulonglong2 vp = *(const ulonglong2*)(g_V2 + (size_t)g*IDM + lane*4);
    float4 w2r = *(const float4*)(We2 + lane*4);
    float nvx, nvy, nvz, nvw;
    unpack2(vp.x, nvx, nvy); unpack2(vp.y, nvz, nvw);
    u64 nv01 = pack2(-nvx, -nvy), nv23 = pack2(-nvz, -nvw);
    u64 w01 = pack2(w2r.x*INV_SQRT2, w2r.y*INV_SQRT2);
    u64 w23 = pack2(w2r.z*INV_SQRT2, w2r.w*INV_SQRT2);
    u64 C0_2 = pack2(ERF_C0, ERF_C0), C1_2 = pack2(ERF_C1, ERF_C1);
    float cconst = __ldg(&be2[0]) - __ldg(&g_SV[g]);

    const float* Ub = g_U2 + (size_t)b*NN*IDM + lane*4;
    const unsigned short* lst = lst_s[w];
    int elane = ((lane >> 2) & 1) | (((lane >> 3) & 1) << 1) | (((lane >> 4) & 1) << 2);
    bool hi4 = lane & 16, hi3 = lane & 8, hi2 = lane & 4;

    float runmax = 0.0f;               // diagonal guarantees a 0 entry
    for (int base = 0; base < cnt; base += 8) {
        // this lane's entry metadata + su prefetch (in flight during compute)
        int gidx = base + elane;
        int idxl = lst[min(gidx, cnt-1)];
        float suv = __ldg(&gSUb[idxl]);

        float p[8];
        #pragma unroll
        for (int h = 0; h < 2; h++) {
            int i0 = lst[min(base + 4*h + 0, cnt-1)];
            int i1 = lst[min(base + 4*h + 1, cnt-1)];
            int i2 = lst[min(base + 4*h + 2, cnt-1)];
            int i3 = lst[min(base + 4*h + 3, cnt-1)];
            ulonglong2 U0 = *(const ulonglong2*)(Ub + i0*IDM);
            ulonglong2 U1 = *(const ulonglong2*)(Ub + i1*IDM);
            ulonglong2 U2 = *(const ulonglong2*)(Ub + i2*IDM);
            ulonglong2 U3 = *(const ulonglong2*)(Ub + i3*IDM);
            ulonglong2 UU[4] = {U0, U1, U2, U3};
            #pragma unroll
            for (int e = 0; e < 4; e++) {
                u64 d01 = add2(UU[e].x, nv01);
                u64 d23 = add2(UU[e].y, nv23);
                u64 dd01 = mul2(d01, d01), dd23 = mul2(d23, d23);
                u64 a01 = fma2(dd01, C1_2, C0_2);
                u64 a23 = fma2(dd23, C1_2, C0_2);
                u64 g01 = mul2(d01, a01), g23 = mul2(d23, a23);
                float gx, gy, gz, gw;
                unpack2(g01, gx, gy); unpack2(g23, gz, gw);
                float ex = fast_tanh(gx), ey = fast_tanh(gy);
                float ez = fast_tanh(gz), ew = fast_tanh(gw);
                u64 e01 = pack2(ex, ey), e23 = pack2(ez, ew);
                u64 t01 = mul2(d01, w01), t23 = mul2(d23, w23);
                u64 s2 = fma2(t01, e01, mul2(t23, e23));
                float slo, shi; unpack2(s2, slo, shi);
                p[4*h + e] = slo + shi;
            }
        }
        // segmented butterfly: 8 sums across 32 lanes in 9 shuffles
        float q0 = (hi4 ? p[4] : p[0]) + __shfl_xor_sync(0xffffffffu, hi4 ? p[0] : p[4], 16);
        float q1 = (hi4 ? p[5] : p[1]) + __shfl_xor_sync(0xffffffffu, hi4 ? p[1] : p[5], 16);
        float q2 = (hi4 ? p[6] : p[2]) + __shfl_xor_sync(0xffffffffu, hi4 ? p[2] : p[6], 16);
        float q3 = (hi4 ? p[7] : p[3]) + __shfl_xor_sync(0xffffffffu, hi4 ? p[3] : p[7], 16);
        float r0 = (hi3 ? q2 : q0) + __shfl_xor_sync(0xffffffffu, hi3 ? q0 : q2, 8);
        float r1 = (hi3 ? q3 : q1) + __shfl_xor_sync(0xffffffffu, hi3 ? q1 : q3, 8);
        float s  = (hi2 ? r1 : r0) + __shfl_xor_sync(0xffffffffu, hi2 ? r0 : r1, 4);
        s += __shfl_xor_sync(0xffffffffu, s, 2);
        s += __shfl_xor_sync(0xffffffffu, s, 1);
        float extra = (gidx < cnt) ? (suv + cconst) : -3e38f;
        runmax = fmaxf(runmax, s + extra);
    }
    #pragma unroll
    for (int o = 16; o; o >>= 1)
        runmax = fmaxf(runmax, __shfl_xor_sync(0xffffffffu, runmax, o));
    if (lane == 0) pmax_s[w] = runmax;
    __syncthreads();

    // warp 0: node MLP 64->64->1 + sigmoid
    if (w == 0) {
        float nm = fmaxf(fmaxf(pmax_s[0], pmax_s[1]),
                         fmaxf(pmax_s[2], pmax_s[3]));
        float n1a = fmaxf(fmaf(nm, __ldg(&Wn1[lane]),      __ldg(&bn1[lane])),      0.0f);
        float n1b = fmaxf(fmaf(nm, __ldg(&Wn1[lane + 32]), __ldg(&bn1[lane + 32])), 0.0f);
        n1_s[lane]      = n1a;
        n1_s[lane + 32] = n1b;
        __syncwarp();
        float acc0 = __ldg(&bn2[lane]), acc1 = __ldg(&bn2[lane + 32]);
        #pragma unroll 8
        for (int k = 0; k < HD; k++) {
            float f = n1_s[k];
            acc0 = fmaf(f, __ldg(&Wn2[k*HD + lane]),      acc0);
            acc1 = fmaf(f, __ldg(&Wn2[k*HD + lane + 32]), acc1);
        }
        acc0 = fmaxf(acc0, 0.0f);
        acc1 = fmaxf(acc1, 0.0f);
        float part = fmaf(acc0, __ldg(&Wh[lane]), acc1 * __ldg(&Wh[lane + 32]));
        #pragma unroll
        for (int o = 16; o; o >>= 1) part += __shfl_xor_sync(0xffffffffu, part, o);
        if (lane == 0) {
            float lg = part + __ldg(&bh[0]);
            out[g] = 1.0f / (1.0f + expf(-lg));
        }
    }
}

extern "C" void kernel_launch(void* const* d_in, const int* in_sizes, int n_in,
                              void* d_out, int out_size) {
    const float* bf   = (const float*)d_in[0];
    const float* cls  = (const float*)d_in[1];
    const int*   aid  = (const int*)  d_in[2];
    const float* emb  = (const float*)d_in[3];
    const float* Wcls = (const float*)d_in[4];
    const float* bcls = (const float*)d_in[5];
    const float* Wpos = (const float*)d_in[6];
    const float* bpos = (const float*)d_in[7];
    const float* Win  = (const float*)d_in[8];
    const float* bin  = (const float*)d_in[9];
    const float* Wout = (const float*)d_in[10];
    const float* bout = (const float*)d_in[11];
    const float* We1  = (const float*)d_in[12];
    const float* be1  = (const float*)d_in[13];
    const float* We2  = (const float*)d_in[14];
    const float* be2  = (const float*)d_in[15];
    const float* Wn1  = (const float*)d_in[16];
    const float* bn1  = (const float*)d_in[17];
    const float* Wn2  = (const float*)d_in[18];
    const float* bn2  = (const float*)d_in[19];
    const float* Wh   = (const float*)d_in[20];
    const float* bh   = (const float*)d_in[21];
    float* out = (float*)d_out;

    prep_kernel<<<(BB*NN)/RPB, 256>>>(bf, emb, Wcls, bcls, Wpos, bpos,
                                      Win, bin, Wout, bout, We1, be1, We2);
    main_kernel<<<BB*NN, 128>>>(cls, aid, emb, We2, be2,
                                Wn1, bn1, Wn2, bn2, Wh, bh, out);
}

// round 8
// speedup vs baseline: 1.1645x; 1.1645x over previous
#include <cuda_runtime.h>
#include <math.h>

#define BB 4
#define NN 512
#define HD 64
#define IDM 128
#define PI_F 3.14159265358979323846f
#define INV_SQRT2 0.70710678118654752440f
#define RPB 16           // rows per prep block (grid 128 = one wave)

// tanh-based erf approx: erf(d) ~= tanh(C0*d + C1*d^3)
#define ERF_C0 1.1283791671f
#define ERF_C1 0.1009052923f

// Scratch (device globals: no allocation allowed)
__device__ __align__(16) float g_U2[BB*NN*IDM];   // (A@We1 + be1) / sqrt2
__device__ __align__(16) float g_V2[BB*NN*IDM];   // (C@We1)       / sqrt2
__device__ float g_SU[BB*NN];                     // 0.5 * dot(U, w2)
__device__ float g_SV[BB*NN];

typedef unsigned long long u64;

__device__ __forceinline__ u64 pack2(float lo, float hi) {
    u64 r; asm("mov.b64 %0, {%1, %2};" : "=l"(r) : "f"(lo), "f"(hi)); return r;
}
__device__ __forceinline__ void unpack2(u64 v, float& lo, float& hi) {
    asm("mov.b64 {%0, %1}, %2;" : "=f"(lo), "=f"(hi) : "l"(v));
}
__device__ __forceinline__ u64 fma2(u64 a, u64 b, u64 c) {
    u64 r; asm("fma.rn.f32x2 %0, %1, %2, %3;" : "=l"(r) : "l"(a), "l"(b), "l"(c)); return r;
}
__device__ __forceinline__ u64 add2(u64 a, u64 b) {
    u64 r; asm("add.rn.f32x2 %0, %1, %2;" : "=l"(r) : "l"(a), "l"(b)); return r;
}
__device__ __forceinline__ u64 mul2(u64 a, u64 b) {
    u64 r; asm("mul.rn.f32x2 %0, %1, %2;" : "=l"(r) : "l"(a), "l"(b)); return r;
}
__device__ __forceinline__ float fast_tanh(float x) {
    float y; asm("tanh.approx.f32 %0, %1;" : "=f"(y) : "f"(x)); return y;
}

// ---------------------------------------------------------------------------
// Precompute. Grid 128 (single wave), 256 threads.
// ti = I-index (0..127), half = row-group (8 rows each of 16).
// All weight matrices staged through smem in 32x128 chunks (coalesced float4),
// consumed with conflict-free LDS — removes strided-LDG latency exposure.
// ---------------------------------------------------------------------------
__global__ __launch_bounds__(256) void prep_kernel(
    const float* __restrict__ bf,   const float* __restrict__ emb,
    const float* __restrict__ Wcls, const float* __restrict__ bcls,
    const float* __restrict__ Wpos, const float* __restrict__ bpos,
    const float* __restrict__ Win,  const float* __restrict__ bin,
    const float* __restrict__ Wout, const float* __restrict__ bout,
    const float* __restrict__ We1,  const float* __restrict__ be1,
    const float* __restrict__ We2)
{
    int t = threadIdx.x, lane = t & 31, wid = t >> 5;   // wid 0..7
    int ti = t & 127, half = t >> 7;                    // rows 8*half..8*half+7
    int row0 = blockIdx.x * RPB;

    __shared__ __align__(16) float xs[RPB][HD];        // 4 KB
    __shared__ __align__(16) float featsT[HD][RPB];    // 4 KB, k-major
    __shared__ __align__(16) float ApreT[IDM][RPB];    // 8 KB, k-major
    __shared__ __align__(16) float BpreT[IDM][RPB];    // 8 KB
    __shared__ __align__(16) float WA_s[32*IDM];       // 16 KB weight stage
    __shared__ __align__(16) float WB_s[32*IDM];       // 16 KB weight stage
    __shared__ float p0s[RPB], p1s[RPB];
    __shared__ float partU[8][8], partV[8][8];

    for (int idx = t; idx < RPB*HD/4; idx += 256)
        ((float4*)xs)[idx] = ((const float4*)(bf + row0*HD))[idx];

    // stage Wcls (64x64 = 1024 float4) into WA_s while xs loads are in flight
    for (int idx = t; idx < 1024; idx += 256)
        ((float4*)WA_s)[idx] = ((const float4*)Wcls)[idx];

    if (t < RPB) {
        int row = row0 + t;
        float ang = emb[row*2 + 0] * PI_F;
        float rho = emb[row*2 + 1] * 800.0f;
        float tn = tanf(ang);
        float ic = 1.0f / cosf(ang);
        float lin1 = (1.0f - 1e-5f) / 71.0f;
        float y0 = 160.0f;
        float y1 = 160.0f - lin1 * 320.0f;
        p0s[t] = (-tn * y0 + rho * ic) * (1.0f / 800.0f);
        p1s[t] = (-tn * y1 + rho * ic) * (1.0f / 800.0f);
    }
    __syncthreads();

    // phase 1: feats = relu(x @ Wcls + bcls), 4 rows per pass, 4 passes
    {
        int d = t & 63, rq = t >> 6;     // rq 0..3
        float bc = bcls[d];
        #pragma unroll
        for (int pass = 0; pass < 4; pass++) {
            int r = rq + 4*pass;
            float acc = bc;
            #pragma unroll 8
            for (int k = 0; k < HD; k++) acc = fmaf(xs[r][k], WA_s[k*64 + d], acc);
            featsT[d][r] = fmaxf(acc, 0.0f);
        }
    }
    __syncthreads();

    // phase 2: f_in / f_out for this half's 8 rows, Win/Wout staged per 32-k chunk
    u64 ai[4], ao[4];
    {
        float bi = bin[ti], bo = bout[ti];
        ai[0] = pack2(bi,bi); ai[1] = ai[0]; ai[2] = ai[0]; ai[3] = ai[0];
        ao[0] = pack2(bo,bo); ao[1] = ao[0]; ao[2] = ao[0]; ao[3] = ao[0];
        #pragma unroll
        for (int c = 0; c < HD; c += 32) {
            // stage Win/Wout chunk [32][128]
            for (int idx = t; idx < 32*32; idx += 256) {
                ((float4*)WA_s)[idx] = ((const float4*)(Win  + c*IDM))[idx];
                ((float4*)WB_s)[idx] = ((const float4*)(Wout + c*IDM))[idx];
            }
            __syncthreads();
            #pragma unroll 8
            for (int kk = 0; kk < 32; kk++) {
                int k = c + kk;
                float win = WA_s[kk*IDM + ti], wout = WB_s[kk*IDM + ti];
                u64 wi = pack2(win, win), wo = pack2(wout, wout);
                const ulonglong2* fp = (const ulonglong2*)&featsT[k][8*half];
                ulonglong2 fA = fp[0], fB = fp[1];
                ai[0] = fma2(fA.x, wi, ai[0]);  ao[0] = fma2(fA.x, wo, ao[0]);
                ai[1] = fma2(fA.y, wi, ai[1]);  ao[1] = fma2(fA.y, wo, ao[1]);
                ai[2] = fma2(fB.x, wi, ai[2]);  ao[2] = fma2(fB.x, wo, ao[2]);
                ai[3] = fma2(fB.y, wi, ai[3]);  ao[3] = fma2(fB.y, wo, ao[3]);
            }
            __syncthreads();
        }
        float wp0 = Wpos[ti], wp1 = Wpos[IDM + ti], bp = bpos[ti];
        u64 bp2 = pack2(bp, bp);
        u64* arow = (u64*)&ApreT[ti][8*half];
        u64* brow = (u64*)&BpreT[ti][8*half];
        #pragma unroll
        for (int q = 0; q < 4; q++) {
            int r0 = 8*half + 2*q;
            float peA = fmaf(p0s[r0],   wp0, p1s[r0]   * wp1);
            float peB = fmaf(p0s[r0+1], wp0, p1s[r0+1] * wp1);
            u64 pe = pack2(peA, peB);
            arow[q] = add2(ai[q], add2(pe, bp2));
            brow[q] = add2(ao[q], pe);
        }
    }
    __syncthreads();

    // phase 3: U = Apre @ We1 + be1, V = Bpre @ We1, We1 staged per 32-k chunk
    float uu[8], vv[8];
    {
        float b1 = be1[ti];
        u64 U[4], V[4];
        U[0] = pack2(b1,b1); U[1] = U[0]; U[2] = U[0]; U[3] = U[0];
        V[0] = 0ULL; V[1] = 0ULL; V[2] = 0ULL; V[3] = 0ULL;
        #pragma unroll
        for (int c = 0; c < IDM; c += 32) {
            for (int idx = t; idx < 32*32; idx += 256)
                ((float4*)WA_s)[idx] = ((const float4*)(We1 + c*IDM))[idx];
            __syncthreads();
            #pragma unroll 8
            for (int kk = 0; kk < 32; kk++) {
                int k = c + kk;
                float w = WA_s[kk*IDM + ti];
                u64 w2 = pack2(w, w);
                const ulonglong2* ap = (const ulonglong2*)&ApreT[k][8*half];
                const ulonglong2* cp = (const ulonglong2*)&BpreT[k][8*half];
                ulonglong2 aA = ap[0], aB = ap[1];
                ulonglong2 cA = cp[0], cB = cp[1];
                U[0] = fma2(aA.x, w2, U[0]);  V[0] = fma2(cA.x, w2, V[0]);
                U[1] = fma2(aA.y, w2, U[1]);  V[1] = fma2(cA.y, w2, V[1]);
                U[2] = fma2(aB.x, w2, U[2]);  V[2] = fma2(cB.x, w2, V[2]);
                U[3] = fma2(aB.y, w2, U[3]);  V[3] = fma2(cB.y, w2, V[3]);
            }
            __syncthreads();
        }
        u64 is2 = pack2(INV_SQRT2, INV_SQRT2);
        #pragma unroll
        for (int q = 0; q < 4; q++) {
            U[q] = mul2(U[q], is2);  V[q] = mul2(V[q], is2);
            unpack2(U[q], uu[2*q], uu[2*q+1]);
            unpack2(V[q], vv[2*q], vv[2*q+1]);
        }
    }

    float w2s = We2[ti] * INV_SQRT2;
    #pragma unroll
    for (int r = 0; r < 8; r++) {
        int row = row0 + 8*half + r;
        g_U2[row*IDM + ti] = uu[r];
        g_V2[row*IDM + ti] = vv[r];
        float su = uu[r] * w2s, sv = vv[r] * w2s;
        #pragma unroll
        for (int o = 16; o; o >>= 1) {
            su += __shfl_xor_sync(0xffffffffu, su, o);
            sv += __shfl_xor_sync(0xffffffffu, sv, o);
        }
        if (lane == 0) { partU[wid][r] = su; partV[wid][r] = sv; }
    }
    __syncthreads();
    if (t < RPB) {
        int r = t, h = r >> 3, rr = r & 7, w0 = 4*h;
        g_SU[row0 + r] = partU[w0][rr] + partU[w0+1][rr]
                       + partU[w0+2][rr] + partU[w0+3][rr];
    } else if (t < 2*RPB) {
        int r = t - RPB, h = r >> 3, rr = r & 7, w0 = 4*h;
        g_SV[row0 + r] = partV[w0][rr] + partV[w0+1][rr]
                       + partV[w0+2][rr] + partV[w0+3][rr];
    }
}

// ---------------------------------------------------------------------------
// Main: ONE column per 128-thread block (2048 blocks). Each warp builds and
// consumes its own quarter-range list. Batch-8 entries per iteration,
// DOUBLE-BUFFERED: next batch's U-row gathers + su prefetch are issued before
// the current batch's compute + shuffle-reduce chain.
// ---------------------------------------------------------------------------
__global__ __launch_bounds__(128) void main_kernel(
    const float* __restrict__ cls, const int* __restrict__ aid,
    const float* __restrict__ emb,
    const float* __restrict__ We2, const float* __restrict__ be2,
    const float* __restrict__ Wn1, const float* __restrict__ bn1,
    const float* __restrict__ Wn2, const float* __restrict__ bn2,
    const float* __restrict__ Wh,  const float* __restrict__ bh,
    float* __restrict__ out)
{
    __shared__ unsigned short lst_s[4][128];
    __shared__ float pmax_s[4];
    __shared__ float n1_s[HD];

    int t = threadIdx.x, lane = t & 31, w = t >> 5;
    int g = blockIdx.x;
    int b = g >> 9;

    float cj = __ldg(&cls[g]);
    if (cj < 0.4f) {                   // sigmoid(-1e6) == 0 in f32
        if (t == 0) out[g] = 0.0f;
        return;
    }
    float aj  = __ldg(&emb[2*g]) * PI_F;
    int   idj = __ldg(&aid[g]);

    // per-warp compacted list over i in [128w, 128w+128)
    int cnt = 0;
    {
        unsigned short* lst = lst_s[w];
        int gbase = b*NN + 128*w;
        #pragma unroll
        for (int c = 0; c < 128; c += 32) {
            int gi = gbase + c + lane;
            float ci = __ldg(&cls[gi]);
            float ai = __ldg(&emb[2*gi]) * PI_F;
            int  idi = __ldg(&aid[gi]);
            bool p = (fabsf(ai - aj) < 0.5f) &&
                     ((ci > cj) || ((ci == cj) && (idi > idj)));
            unsigned m = __ballot_sync(0xffffffffu, p);
            if (p) lst[cnt + __popc(m & ((1u << lane) - 1u))]
                       = (unsigned short)(128*w + c + lane);
            cnt += __popc(m);
        }
    }

    // per-column constants
    const float* gSUb = g_SU + b*NN;
    ulonglong2 vp = *(const ulonglong2*)(g_V2 + (size_t)g*IDM + lane*4);
    float4 w2r = *(const float4*)(We2 + lane*4);
    float nvx, nvy, nvz, nvw;
    unpack2(vp.x, nvx, nvy); unpack2(vp.y, nvz, nvw);
    u64 nv01 = pack2(-nvx, -nvy), nv23 = pack2(-nvz, -nvw);
    u64 w01 = pack2(w2r.x*INV_SQRT2, w2r.y*INV_SQRT2);
    u64 w23 = pack2(w2r.z*INV_SQRT2, w2r.w*INV_SQRT2);
    u64 C0_2 = pack2(ERF_C0, ERF_C0), C1_2 = pack2(ERF_C1, ERF_C1);
    float cconst = __ldg(&be2[0]) - __ldg(&g_SV[g]);

    const float* Ub = g_U2 + (size_t)b*NN*IDM + lane*4;
    const unsigned short* lst = lst_s[w];
    int elane = ((lane >> 2) & 1) | (((lane >> 3) & 1) << 1) | (((lane >> 4) & 1) << 2);
    bool hi4 = lane & 16, hi3 = lane & 8, hi2 = lane & 4;

    float runmax = 0.0f;               // diagonal guarantees a 0 entry
    if (cnt > 0) {
        // prologue: load batch 0
        ulonglong2 UP[8];
        float su_p;
        {
            #pragma unroll
            for (int e = 0; e < 8; e++) {
                int idx = lst[min(e, cnt-1)];
                UP[e] = *(const ulonglong2*)(Ub + idx*IDM);
            }
            int idxl = lst[min(elane, cnt-1)];
            su_p = __ldg(&gSUb[idxl]);
        }

        for (int base = 0; base < cnt; base += 8) {
            // prefetch next batch before consuming the current one
            ulonglong2 UN[8];
            float su_n = 0.0f;
            int nb = base + 8;
            if (nb < cnt) {
                #pragma unroll
                for (int e = 0; e < 8; e++) {
                    int idx = lst[min(nb + e, cnt-1)];
                    UN[e] = *(const ulonglong2*)(Ub + idx*IDM);
                }
                int idxl = lst[min(nb + elane, cnt-1)];
                su_n = __ldg(&gSUb[idxl]);
            }

            float p[8];
            #pragma unroll
            for (int e = 0; e < 8; e++) {
                u64 d01 = add2(UP[e].x, nv01);
                u64 d23 = add2(UP[e].y, nv23);
                u64 dd01 = mul2(d01, d01), dd23 = mul2(d23, d23);
                u64 a01 = fma2(dd01, C1_2, C0_2);
                u64 a23 = fma2(dd23, C1_2, C0_2);
                u64 g01 = mul2(d01, a01), g23 = mul2(d23, a23);
                float gx, gy, gz, gw;
                unpack2(g01, gx, gy); unpack2(g23, gz, gw);
                float ex = fast_tanh(gx), ey = fast_tanh(gy);
                float ez = fast_tanh(gz), ew = fast_tanh(gw);
                u64 e01 = pack2(ex, ey), e23 = pack2(ez, ew);
                u64 t01 = mul2(d01, w01), t23 = mul2(d23, w23);
                u64 s2 = fma2(t01, e01, mul2(t23, e23));
                float slo, shi; unpack2(s2, slo, shi);
                p[e] = slo + shi;
            }
            // segmented butterfly: 8 sums across 32 lanes in 9 shuffles
            float q0 = (hi4 ? p[4] : p[0]) + __shfl_xor_sync(0xffffffffu, hi4 ? p[0] : p[4], 16);
            float q1 = (hi4 ? p[5] : p[1]) + __shfl_xor_sync(0xffffffffu, hi4 ? p[1] : p[5], 16);
            float q2 = (hi4 ? p[6] : p[2]) + __shfl_xor_sync(0xffffffffu, hi4 ? p[2] : p[6], 16);
            float q3 = (hi4 ? p[7] : p[3]) + __shfl_xor_sync(0xffffffffu, hi4 ? p[3] : p[7], 16);
            float r0 = (hi3 ? q2 : q0) + __shfl_xor_sync(0xffffffffu, hi3 ? q0 : q2, 8);
            float r1 = (hi3 ? q3 : q1) + __shfl_xor_sync(0xffffffffu, hi3 ? q1 : q3, 8);
            float s  = (hi2 ? r1 : r0) + __shfl_xor_sync(0xffffffffu, hi2 ? r0 : r1, 4);
            s += __shfl_xor_sync(0xffffffffu, s, 2);
            s += __shfl_xor_sync(0xffffffffu, s, 1);
            int gidx = base + elane;
            float extra = (gidx < cnt) ? (su_p + cconst) : -3e38f;
            runmax = fmaxf(runmax, s + extra);

            #pragma unroll
            for (int e = 0; e < 8; e++) UP[e] = UN[e];
            su_p = su_n;
        }
        #pragma unroll
        for (int o = 16; o; o >>= 1)
            runmax = fmaxf(runmax, __shfl_xor_sync(0xffffffffu, runmax, o));
    }
    if (lane == 0) pmax_s[w] = runmax;
    __syncthreads();

    // warp 0: node MLP 64->64->1 + sigmoid
    if (w == 0) {
        float nm = fmaxf(fmaxf(pmax_s[0], pmax_s[1]),
                         fmaxf(pmax_s[2], pmax_s[3]));
        float n1a = fmaxf(fmaf(nm, __ldg(&Wn1[lane]),      __ldg(&bn1[lane])),      0.0f);
        float n1b = fmaxf(fmaf(nm, __ldg(&Wn1[lane + 32]), __ldg(&bn1[lane + 32])), 0.0f);
        n1_s[lane]      = n1a;
        n1_s[lane + 32] = n1b;
        __syncwarp();
        float acc0 = __ldg(&bn2[lane]), acc1 = __ldg(&bn2[lane + 32]);
        #pragma unroll 8
        for (int k = 0; k < HD; k++) {
            float f = n1_s[k];
            acc0 = fmaf(f, __ldg(&Wn2[k*HD + lane]),      acc0);
            acc1 = fmaf(f, __ldg(&Wn2[k*HD + lane + 32]), acc1);
        }
        acc0 = fmaxf(acc0, 0.0f);
        acc1 = fmaxf(acc1, 0.0f);
        float part = fmaf(acc0, __ldg(&Wh[lane]), acc1 * __ldg(&Wh[lane + 32]));
        #pragma unroll
        for (int o = 16; o; o >>= 1) part += __shfl_xor_sync(0xffffffffu, part, o);
        if (lane == 0) {
            float lg = part + __ldg(&bh[0]);
            out[g] = 1.0f / (1.0f + expf(-lg));
        }
    }
}

extern "C" void kernel_launch(void* const* d_in, const int* in_sizes, int n_in,
                              void* d_out, int out_size) {
    const float* bf   = (const float*)d_in[0];
    const float* cls  = (const float*)d_in[1];
    const int*   aid  = (const int*)  d_in[2];
    const float* emb  = (const float*)d_in[3];
    const float* Wcls = (const float*)d_in[4];
    const float* bcls = (const float*)d_in[5];
    const float* Wpos = (const float*)d_in[6];
    const float* bpos = (const float*)d_in[7];
    const float* Win  = (const float*)d_in[8];
    const float* bin  = (const float*)d_in[9];
    const float* Wout = (const float*)d_in[10];
    const float* bout = (const float*)d_in[11];
    const float* We1  = (const float*)d_in[12];
    const float* be1  = (const float*)d_in[13];
    const float* We2  = (const float*)d_in[14];
    const float* be2  = (const float*)d_in[15];
    const float* Wn1  = (const float*)d_in[16];
    const float* bn1  = (const float*)d_in[17];
    const float* Wn2  = (const float*)d_in[18];
    const float* bn2  = (const float*)d_in[19];
    const float* Wh   = (const float*)d_in[20];
    const float* bh   = (const float*)d_in[21];
    float* out = (float*)d_out;

    prep_kernel<<<(BB*NN)/RPB, 256>>>(bf, emb, Wcls, bcls, Wpos, bpos,
                                      Win, bin, Wout, bout, We1, be1, We2);
    main_kernel<<<BB*NN, 128>>>(cls, aid, emb, We2, be2,
                                Wn1, bn1, Wn2, bn2, Wh, bh, out);
}